// round 9
// baseline (speedup 1.0000x reference)
#include <cuda_runtime.h>
#include <cuda_bf16.h>
#include <math.h>
#include <stdint.h>

// Problem dims (fixed): x [2,2048,2048] -> T=4096 tokens, H=2048, I=8192
#define T_TOK 4096
#define HDIM  2048
#define IDIM  8192
#define NGATE 16384   // 2*I rows in w_gate
#define PITCH 80      // padded smem row pitch (bytes) for bf16 64B k-chunks

// ---------------- device scratch (static, allocation-free) ----------------
__device__ double        d_abssum[2];
__device__ float         d_wscale[2];
__device__ float         d_winv[2];
__device__ __nv_bfloat16 d_wqg[(long long)NGATE * HDIM];   // ternary gate/up (bf16)
__device__ __nv_bfloat16 d_wqd[(long long)HDIM * IDIM];    // ternary down (bf16)
__device__ signed char   d_wqg8[(long long)NGATE * HDIM];  // same, int8
__device__ signed char   d_wqd8[(long long)HDIM * IDIM];
__device__ __nv_bfloat16 d_xq[(long long)T_TOK * HDIM];    // quant acts L1 (bf16 ints)
__device__ signed char   d_xq8[(long long)T_TOK * HDIM];
__device__ float         d_as1[T_TOK];
__device__ float         d_h[(long long)T_TOK * IDIM];     // SwiGLU output (fp32)
__device__ __nv_bfloat16 d_hq[(long long)T_TOK * IDIM];    // quant acts L2
__device__ signed char   d_hq8[(long long)T_TOK * IDIM];
__device__ float         d_as2[T_TOK];

// ---------------- PTX helpers (base PTX only) ----------------
__device__ __forceinline__ uint32_t smem_u32(const void* p) {
    return (uint32_t)__cvta_generic_to_shared(p);
}
__device__ __forceinline__ void cpa16(uint32_t s, const void* g) {
    asm volatile("cp.async.cg.shared.global [%0], [%1], 16;" :: "r"(s), "l"(g));
}
__device__ __forceinline__ void cp_commit() {
    asm volatile("cp.async.commit_group;");
}
__device__ __forceinline__ void barsync() {
    asm volatile("bar.sync 0;" ::: "memory");
}
__device__ __forceinline__ void ldsm4(uint32_t* r, uint32_t a) {
    asm volatile("ldmatrix.sync.aligned.m8n8.x4.shared.b16 {%0,%1,%2,%3}, [%4];"
        : "=r"(r[0]), "=r"(r[1]), "=r"(r[2]), "=r"(r[3]) : "r"(a));
}
__device__ __forceinline__ void mma_bf16(float* c, const uint32_t* a, const uint32_t* b) {
    asm volatile(
        "mma.sync.aligned.m16n8k16.row.col.f32.bf16.bf16.f32 "
        "{%0,%1,%2,%3}, {%4,%5,%6,%7}, {%8,%9}, {%0,%1,%2,%3};"
        : "+f"(c[0]), "+f"(c[1]), "+f"(c[2]), "+f"(c[3])
        : "r"(a[0]), "r"(a[1]), "r"(a[2]), "r"(a[3]), "r"(b[0]), "r"(b[1]));
}
__device__ __forceinline__ float silu_mul(float g, float v) {
    return g / (1.f + expf(-g)) * v;
}

// ---------------- scalar pre-passes ----------------
__global__ void k_zero() { d_abssum[0] = 0.0; d_abssum[1] = 0.0; }

// both weight reductions in one launch: blocks [0,2048) gate, [2048,3072) down
__global__ void k_abssum2(const float* __restrict__ wg, const float* __restrict__ wd) {
    const float* w; long long n; int slot, bid, nb;
    if (blockIdx.x < 2048) { w = wg; n = (long long)NGATE * HDIM; slot = 0; bid = blockIdx.x; nb = 2048; }
    else                   { w = wd; n = (long long)HDIM * IDIM;  slot = 1; bid = blockIdx.x - 2048; nb = 1024; }
    float s = 0.f;
    long long stride = (long long)nb * 256;
    for (long long i = (long long)bid * 256 + threadIdx.x; i < n; i += stride)
        s += fabsf(w[i]);
    #pragma unroll
    for (int o = 16; o > 0; o >>= 1) s += __shfl_xor_sync(0xffffffffu, s, o);
    __shared__ double sb[8];
    int wid = threadIdx.x >> 5, lane = threadIdx.x & 31;
    if (lane == 0) sb[wid] = (double)s;
    __syncthreads();
    if (threadIdx.x == 0) {
        double t = 0.0;
        #pragma unroll
        for (int i = 0; i < 8; i++) t += sb[i];
        atomicAdd(&d_abssum[slot], t);
    }
}

__global__ void k_wscale() {
    float m0 = (float)(d_abssum[0] / (double)((long long)NGATE * HDIM));
    float m1 = (float)(d_abssum[1] / (double)((long long)HDIM * IDIM));
    float s0 = 1.f / fmaxf(m0, 1e-5f);
    float s1 = 1.f / fmaxf(m1, 1e-5f);
    d_wscale[0] = s0; d_wscale[1] = s1;
    d_winv[0] = 1.f / s0; d_winv[1] = 1.f / s1;
}

// ternarize both weights -> bf16 AND int8; blocks [0,4096) gate, [4096,6144) down
__global__ void k_wquant2(const float4* __restrict__ wg, const float4* __restrict__ wd) {
    const float4* w; long long n4; int which, bid, nb;
    if (blockIdx.x < 4096) { w = wg; n4 = (long long)NGATE * HDIM / 4; which = 0; bid = blockIdx.x; nb = 4096; }
    else                   { w = wd; n4 = (long long)HDIM * IDIM / 4;  which = 1; bid = blockIdx.x - 4096; nb = 2048; }
    float s = d_wscale[which];
    __nv_bfloat162* q2 = reinterpret_cast<__nv_bfloat162*>(which ? d_wqd : d_wqg);
    char4* q8 = reinterpret_cast<char4*>(which ? d_wqd8 : d_wqg8);
    long long stride = (long long)nb * 256;
    for (long long i = (long long)bid * 256 + threadIdx.x; i < n4; i += stride) {
        float4 v = w[i];
        float a = fminf(fmaxf(rintf(v.x * s), -1.f), 1.f);
        float b = fminf(fmaxf(rintf(v.y * s), -1.f), 1.f);
        float c = fminf(fmaxf(rintf(v.z * s), -1.f), 1.f);
        float d = fminf(fmaxf(rintf(v.w * s), -1.f), 1.f);
        q2[i * 2 + 0] = __floats2bfloat162_rn(a, b);
        q2[i * 2 + 1] = __floats2bfloat162_rn(c, d);
        q8[i] = make_char4((signed char)a, (signed char)b, (signed char)c, (signed char)d);
    }
}

// ---------------- block reduction helper ----------------
__device__ __forceinline__ float block_reduce(float v, bool isMax) {
    __shared__ float sb[8];
    __syncthreads();
    #pragma unroll
    for (int o = 16; o > 0; o >>= 1) {
        float t = __shfl_xor_sync(0xffffffffu, v, o);
        v = isMax ? fmaxf(v, t) : (v + t);
    }
    int wid = threadIdx.x >> 5, lane = threadIdx.x & 31;
    if (lane == 0) sb[wid] = v;
    __syncthreads();
    float r;
    if (isMax) {
        r = fmaxf(fmaxf(fmaxf(sb[0], sb[1]), fmaxf(sb[2], sb[3])),
                  fmaxf(fmaxf(sb[4], sb[5]), fmaxf(sb[6], sb[7])));
    } else {
        r = sb[0] + sb[1] + sb[2] + sb[3] + sb[4] + sb[5] + sb[6] + sb[7];
    }
    return r;
}

// ---------------- RMSNorm + per-token int8 quant (bf16 + s8 outputs) -------
template <int HID, int VPT>
__global__ void __launch_bounds__(256) k_actquant(
    const float* __restrict__ x, const float* __restrict__ g,
    __nv_bfloat16* __restrict__ q16, signed char* __restrict__ q8,
    float* __restrict__ ascale)
{
    long long t = blockIdx.x;
    const float* xr = x + t * HID;
    float v[VPT];
    float ss = 0.f;
    #pragma unroll
    for (int j = 0; j < VPT; j++) {
        float f = xr[threadIdx.x + j * 256];
        v[j] = f;
        ss += f * f;
    }
    float var = block_reduce(ss, false) * (1.f / (float)HID);
    float r = rsqrtf(var + 1e-5f);
    float amax = 0.f;
    #pragma unroll
    for (int j = 0; j < VPT; j++) {
        float xn = v[j] * r * g[threadIdx.x + j * 256];
        v[j] = xn;
        amax = fmaxf(amax, fabsf(xn));
    }
    amax = block_reduce(amax, true);
    float s = 127.f / fmaxf(amax, 1e-5f);
    __nv_bfloat16* qr = q16 + t * HID;
    signed char* qr8 = q8 + t * HID;
    #pragma unroll
    for (int j = 0; j < VPT; j++) {
        float qf = fminf(fmaxf(rintf(v[j] * s), -128.f), 127.f);
        qr[threadIdx.x + j * 256] = __float2bfloat16(qf);  // exact int
        qr8[threadIdx.x + j * 256] = (signed char)qf;
    }
    if (threadIdx.x == 0) ascale[t] = 1.f / s;
}

// =====================================================================
// GEMM1 mixed-pipe: 512 thr = 12 HMMA warps (cols 0-95) + 4 dp4a warps
// (cols 96-127), for BOTH gate and v halves; SwiGLU epilogue -> d_h.
// k-chunk = 32 elements. Stage layout (S1=31744 bytes):
//   A16 @0 (128x80) | G16 @10240 (96x80) | V16 @17920 (96x80)
//   A8  @25600 (4KB packed) | G8 @29696 (1KB) | V8 @30720 (1KB)
// int8 "packed" layout: addr(row,k) = (row>>2)*128 + (row&3)*32 + k
// =====================================================================
#define S1 31744

#define G1_LOAD(buf, kt)                                                          \
{                                                                                 \
    const uint32_t st = sb + (buf) * S1;                                          \
    { int row = tid >> 2, seg = tid & 3;                                          \
      cpa16(st + (uint32_t)row * PITCH + seg * 16,                                \
            Ag16 + (long long)row * (HDIM * 2) + (kt) * 64 + seg * 16); }         \
    if (tid < 384) { int row = tid >> 2, seg = tid & 3;                           \
      cpa16(st + 10240 + (uint32_t)row * PITCH + seg * 16,                        \
            Gg16 + (long long)row * (HDIM * 2) + (kt) * 64 + seg * 16); }         \
    if (tid >= 128) { int u = tid - 128, row = u >> 2, seg = u & 3;               \
      cpa16(st + 17920 + (uint32_t)row * PITCH + seg * 16,                        \
            Vg16 + (long long)row * (HDIM * 2) + (kt) * 64 + seg * 16); }         \
    if (tid < 256) { int row = tid >> 1, seg = tid & 1;                           \
      cpa16(st + 25600 + (uint32_t)((row >> 2) * 128 + (row & 3) * 32 + seg * 16),\
            Ag8 + (long long)row * HDIM + (kt) * 32 + seg * 16); }                \
    if (tid < 64) { int col = tid >> 1, seg = tid & 1;                            \
      cpa16(st + 29696 + (uint32_t)((col >> 2) * 128 + (col & 3) * 32 + seg * 16),\
            Gg8 + (long long)col * HDIM + (kt) * 32 + seg * 16); }                \
    if (tid >= 448) { int u = tid - 448, col = u >> 1, seg = u & 1;               \
      cpa16(st + 30720 + (uint32_t)((col >> 2) * 128 + (col & 3) * 32 + seg * 16),\
            Vg8 + (long long)col * HDIM + (kt) * 32 + seg * 16); }                \
    cp_commit();                                                                  \
}

__global__ void __launch_bounds__(512, 1) k_gemm1() {
    extern __shared__ char smem[];
    const int tid = threadIdx.x;
    const int wid = tid >> 5, l = tid & 31;
    const int mBase = blockIdx.y * 128;
    const int nBase = blockIdx.x * 128;
    const uint32_t sb = smem_u32(smem);

    const char* Ag16 = (const char*)d_xq  + (long long)mBase * (HDIM * 2);
    const char* Gg16 = (const char*)d_wqg + (long long)nBase * (HDIM * 2);
    const char* Vg16 = (const char*)d_wqg + (long long)(nBase + IDIM) * (HDIM * 2);
    const signed char* Ag8 = d_xq8  + (long long)mBase * HDIM;
    const signed char* Gg8 = d_wqg8 + (long long)(nBase + 96) * HDIM;
    const signed char* Vg8 = d_wqg8 + (long long)(nBase + IDIM + 96) * HDIM;

    const int NK = HDIM / 32;   // 64 chunks

    G1_LOAD(0, 0);

    if (wid < 12) {
        // ---- HMMA warps: 2(m) x 6(n); warp tile M=64, N=16 per operand ----
        const int tm = wid / 6, tn = wid % 6;
        const uint32_t aoff = (uint32_t)(tm * 64 + (l & 15)) * PITCH + (l >> 4) * 16;
        const uint32_t boff = (uint32_t)(tn * 16 + ((l >> 4) << 3) + (l & 7)) * PITCH
                            + ((l >> 3) & 1) * 16;
        float accg[4][2][4] = {};
        float accv[4][2][4] = {};

        for (int kt = 0; kt < NK; kt++) {
            const int buf = kt & 1;
            if (kt + 1 < NK) {
                G1_LOAD(buf ^ 1, kt + 1);
                asm volatile("cp.async.wait_group 1;");
            } else {
                asm volatile("cp.async.wait_group 0;");
            }
            barsync();
            const uint32_t As = sb + buf * S1;
            const uint32_t Gs = As + 10240, Vs = As + 17920;
            #pragma unroll
            for (int ks = 0; ks < 2; ks++) {
                uint32_t a[4][4];
                #pragma unroll
                for (int mf = 0; mf < 4; mf++)
                    ldsm4(a[mf], As + aoff + mf * (16 * PITCH) + ks * 32);
                uint32_t bg[4], bv[4];
                ldsm4(bg, Gs + boff + ks * 32);
                ldsm4(bv, Vs + boff + ks * 32);
                #pragma unroll
                for (int mf = 0; mf < 4; mf++) {
                    #pragma unroll
                    for (int nf = 0; nf < 2; nf++) {
                        mma_bf16(accg[mf][nf], a[mf], &bg[nf * 2]);
                        mma_bf16(accv[mf][nf], a[mf], &bv[nf * 2]);
                    }
                }
            }
            barsync();
        }

        // epilogue
        const float wiv = d_winv[0];
        #pragma unroll
        for (int mf = 0; mf < 4; mf++) {
            const int r0 = mBase + tm * 64 + mf * 16 + (l >> 2);
            const float s0 = d_as1[r0] * wiv;
            const float s1 = d_as1[r0 + 8] * wiv;
            float* h0 = d_h + (long long)r0 * IDIM;
            float* h1 = d_h + (long long)(r0 + 8) * IDIM;
            #pragma unroll
            for (int nf = 0; nf < 2; nf++) {
                const int c0 = nBase + tn * 16 + nf * 8 + (l & 3) * 2;
                float2 o0, o1;
                o0.x = silu_mul(accg[mf][nf][0] * s0, accv[mf][nf][0] * s0);
                o0.y = silu_mul(accg[mf][nf][1] * s0, accv[mf][nf][1] * s0);
                o1.x = silu_mul(accg[mf][nf][2] * s1, accv[mf][nf][2] * s1);
                o1.y = silu_mul(accg[mf][nf][3] * s1, accv[mf][nf][3] * s1);
                *(float2*)(h0 + c0) = o0;
                *(float2*)(h1 + c0) = o1;
            }
        }
    } else {
        // ---- dp4a warps: 1 gate col + 1 v col per thread, 32 rows each ----
        const int dwid = wid - 12;
        const int trow = l >> 3;           // rows trow + 4j
        const int tcol = l & 7;
        const int c = dwid * 8 + tcol;     // local int8 col 0..31
        int accg[32] = {};
        int accv[32] = {};

        for (int kt = 0; kt < NK; kt++) {
            const int buf = kt & 1;
            if (kt + 1 < NK) {
                G1_LOAD(buf ^ 1, kt + 1);
                asm volatile("cp.async.wait_group 1;");
            } else {
                asm volatile("cp.async.wait_group 0;");
            }
            barsync();
            const char* base = smem + buf * S1;
            const char* A8 = base + 25600;
            const char* G8 = base + 29696;
            const char* V8 = base + 30720;
            const uint32_t bo = (uint32_t)((c >> 2) * 128 + (c & 3) * 32);
            const int4 bg0 = *(const int4*)(G8 + bo);
            const int4 bg1 = *(const int4*)(G8 + bo + 16);
            const int4 bv0 = *(const int4*)(V8 + bo);
            const int4 bv1 = *(const int4*)(V8 + bo + 16);
            #pragma unroll
            for (int j = 0; j < 32; j++) {
                const char* ap = A8 + j * 128 + trow * 32;
                const int4 a0 = *(const int4*)(ap);
                const int4 a1 = *(const int4*)(ap + 16);
                int sg = accg[j], sv = accv[j];
                sg = __dp4a(a0.x, bg0.x, sg); sv = __dp4a(a0.x, bv0.x, sv);
                sg = __dp4a(a0.y, bg0.y, sg); sv = __dp4a(a0.y, bv0.y, sv);
                sg = __dp4a(a0.z, bg0.z, sg); sv = __dp4a(a0.z, bv0.z, sv);
                sg = __dp4a(a0.w, bg0.w, sg); sv = __dp4a(a0.w, bv0.w, sv);
                sg = __dp4a(a1.x, bg1.x, sg); sv = __dp4a(a1.x, bv1.x, sv);
                sg = __dp4a(a1.y, bg1.y, sg); sv = __dp4a(a1.y, bv1.y, sv);
                sg = __dp4a(a1.z, bg1.z, sg); sv = __dp4a(a1.z, bv1.z, sv);
                sg = __dp4a(a1.w, bg1.w, sg); sv = __dp4a(a1.w, bv1.w, sv);
                accg[j] = sg; accv[j] = sv;
            }
            barsync();
        }

        const float wiv = d_winv[0];
        const int gc = nBase + 96 + c;
        #pragma unroll
        for (int j = 0; j < 32; j++) {
            const int row = mBase + j * 4 + trow;
            const float sc = d_as1[row] * wiv;
            d_h[(long long)row * IDIM + gc] =
                silu_mul((float)accg[j] * sc, (float)accv[j] * sc);
        }
    }
}

// =====================================================================
// GEMM2 mixed-pipe: hq @ w_down^T -> out. Same split, single B operand.
// Stage (S2=23040): A16 @0 | B16 @10240 (96x80) | A8 @17920 | B8 @22016
// =====================================================================
#define S2 23040

#define G2_LOAD(buf, kt)                                                          \
{                                                                                 \
    const uint32_t st = sb + (buf) * S2;                                          \
    { int row = tid >> 2, seg = tid & 3;                                          \
      cpa16(st + (uint32_t)row * PITCH + seg * 16,                                \
            Ag16 + (long long)row * (IDIM * 2) + (kt) * 64 + seg * 16); }         \
    if (tid < 384) { int row = tid >> 2, seg = tid & 3;                           \
      cpa16(st + 10240 + (uint32_t)row * PITCH + seg * 16,                        \
            Bg16 + (long long)row * (IDIM * 2) + (kt) * 64 + seg * 16); }         \
    if (tid < 256) { int row = tid >> 1, seg = tid & 1;                           \
      cpa16(st + 17920 + (uint32_t)((row >> 2) * 128 + (row & 3) * 32 + seg * 16),\
            Ag8 + (long long)row * IDIM + (kt) * 32 + seg * 16); }                \
    if (tid >= 448) { int u = tid - 448, col = u >> 1, seg = u & 1;               \
      cpa16(st + 22016 + (uint32_t)((col >> 2) * 128 + (col & 3) * 32 + seg * 16),\
            Bg8 + (long long)col * IDIM + (kt) * 32 + seg * 16); }                \
    cp_commit();                                                                  \
}

__global__ void __launch_bounds__(512, 1) k_gemm2(float* __restrict__ out) {
    extern __shared__ char smem[];
    const int tid = threadIdx.x;
    const int wid = tid >> 5, l = tid & 31;
    const int mBase = blockIdx.y * 128;
    const int nBase = blockIdx.x * 128;
    const uint32_t sb = smem_u32(smem);

    const char* Ag16 = (const char*)d_hq  + (long long)mBase * (IDIM * 2);
    const char* Bg16 = (const char*)d_wqd + (long long)nBase * (IDIM * 2);
    const signed char* Ag8 = d_hq8  + (long long)mBase * IDIM;
    const signed char* Bg8 = d_wqd8 + (long long)(nBase + 96) * IDIM;

    const int NK = IDIM / 32;   // 256 chunks

    G2_LOAD(0, 0);

    if (wid < 12) {
        const int tm = wid / 6, tn = wid % 6;
        const uint32_t aoff = (uint32_t)(tm * 64 + (l & 15)) * PITCH + (l >> 4) * 16;
        const uint32_t boff = (uint32_t)(tn * 16 + ((l >> 4) << 3) + (l & 7)) * PITCH
                            + ((l >> 3) & 1) * 16;
        float acc[4][2][4] = {};

        for (int kt = 0; kt < NK; kt++) {
            const int buf = kt & 1;
            if (kt + 1 < NK) {
                G2_LOAD(buf ^ 1, kt + 1);
                asm volatile("cp.async.wait_group 1;");
            } else {
                asm volatile("cp.async.wait_group 0;");
            }
            barsync();
            const uint32_t As = sb + buf * S2;
            const uint32_t Bs = As + 10240;
            #pragma unroll
            for (int ks = 0; ks < 2; ks++) {
                uint32_t a[4][4];
                #pragma unroll
                for (int mf = 0; mf < 4; mf++)
                    ldsm4(a[mf], As + aoff + mf * (16 * PITCH) + ks * 32);
                uint32_t b[4];
                ldsm4(b, Bs + boff + ks * 32);
                #pragma unroll
                for (int mf = 0; mf < 4; mf++) {
                    #pragma unroll
                    for (int nf = 0; nf < 2; nf++)
                        mma_bf16(acc[mf][nf], a[mf], &b[nf * 2]);
                }
            }
            barsync();
        }

        const float wiv = d_winv[1];
        #pragma unroll
        for (int mf = 0; mf < 4; mf++) {
            const int r0 = mBase + tm * 64 + mf * 16 + (l >> 2);
            const float s0 = d_as2[r0] * wiv;
            const float s1 = d_as2[r0 + 8] * wiv;
            float* o0p = out + (long long)r0 * HDIM;
            float* o1p = out + (long long)(r0 + 8) * HDIM;
            #pragma unroll
            for (int nf = 0; nf < 2; nf++) {
                const int c0 = nBase + tn * 16 + nf * 8 + (l & 3) * 2;
                float2 o0, o1;
                o0.x = acc[mf][nf][0] * s0;
                o0.y = acc[mf][nf][1] * s0;
                o1.x = acc[mf][nf][2] * s1;
                o1.y = acc[mf][nf][3] * s1;
                *(float2*)(o0p + c0) = o0;
                *(float2*)(o1p + c0) = o1;
            }
        }
    } else {
        const int dwid = wid - 12;
        const int trow = l >> 3;
        const int tcol = l & 7;
        const int c = dwid * 8 + tcol;
        int acc[32] = {};

        for (int kt = 0; kt < NK; kt++) {
            const int buf = kt & 1;
            if (kt + 1 < NK) {
                G2_LOAD(buf ^ 1, kt + 1);
                asm volatile("cp.async.wait_group 1;");
            } else {
                asm volatile("cp.async.wait_group 0;");
            }
            barsync();
            const char* base = smem + buf * S2;
            const char* A8 = base + 17920;
            const char* B8 = base + 22016;
            const uint32_t bo = (uint32_t)((c >> 2) * 128 + (c & 3) * 32);
            const int4 b0 = *(const int4*)(B8 + bo);
            const int4 b1 = *(const int4*)(B8 + bo + 16);
            #pragma unroll
            for (int j = 0; j < 32; j++) {
                const char* ap = A8 + j * 128 + trow * 32;
                const int4 a0 = *(const int4*)(ap);
                const int4 a1 = *(const int4*)(ap + 16);
                int s = acc[j];
                s = __dp4a(a0.x, b0.x, s);
                s = __dp4a(a0.y, b0.y, s);
                s = __dp4a(a0.z, b0.z, s);
                s = __dp4a(a0.w, b0.w, s);
                s = __dp4a(a1.x, b1.x, s);
                s = __dp4a(a1.y, b1.y, s);
                s = __dp4a(a1.z, b1.z, s);
                s = __dp4a(a1.w, b1.w, s);
                acc[j] = s;
            }
            barsync();
        }

        const float wiv = d_winv[1];
        const int gc = nBase + 96 + c;
        #pragma unroll
        for (int j = 0; j < 32; j++) {
            const int row = mBase + j * 4 + trow;
            out[(long long)row * HDIM + gc] = (float)acc[j] * d_as2[row] * wiv;
        }
    }
}

// ---------------- host ----------------
extern "C" void kernel_launch(void* const* d_in, const int* in_sizes, int n_in,
                              void* d_out, int out_size) {
    const float* x      = (const float*)d_in[0];
    const float* w_gate = (const float*)d_in[1];
    const float* g_gate = (const float*)d_in[2];
    const float* w_down = (const float*)d_in[3];
    const float* g_down = (const float*)d_in[4];
    float* out = (float*)d_out;

    __nv_bfloat16* p_xq = nullptr; signed char* p_xq8 = nullptr; float* p_as1 = nullptr;
    float* p_h = nullptr; __nv_bfloat16* p_hq = nullptr; signed char* p_hq8 = nullptr;
    float* p_as2 = nullptr;
    cudaGetSymbolAddress((void**)&p_xq,  d_xq);
    cudaGetSymbolAddress((void**)&p_xq8, d_xq8);
    cudaGetSymbolAddress((void**)&p_as1, d_as1);
    cudaGetSymbolAddress((void**)&p_h,   d_h);
    cudaGetSymbolAddress((void**)&p_hq,  d_hq);
    cudaGetSymbolAddress((void**)&p_hq8, d_hq8);
    cudaGetSymbolAddress((void**)&p_as2, d_as2);

    const int SM1 = 2 * S1;   // 63488
    const int SM2 = 2 * S2;   // 46080
    cudaFuncSetAttribute(k_gemm1, cudaFuncAttributeMaxDynamicSharedMemorySize, SM1);
    cudaFuncSetAttribute(k_gemm2, cudaFuncAttributeMaxDynamicSharedMemorySize, SM2);

    // 0-3) weight scales + ternarize (merged launches)
    k_zero<<<1, 1>>>();
    k_abssum2<<<3072, 256>>>(w_gate, w_down);
    k_wscale<<<1, 1>>>();
    k_wquant2<<<6144, 256>>>((const float4*)w_gate, (const float4*)w_down);

    // 4) RMSNorm + quantize x
    k_actquant<HDIM, HDIM / 256><<<T_TOK, 256>>>(x, g_gate, p_xq, p_xq8, p_as1);

    // 5) GEMM1 + SwiGLU -> h (mixed HMMA + dp4a)
    k_gemm1<<<dim3(IDIM / 128, T_TOK / 128), 512, SM1>>>();

    // 6) RMSNorm + quantize h
    k_actquant<IDIM, IDIM / 256><<<T_TOK, 256>>>(p_h, g_down, p_hq, p_hq8, p_as2);

    // 7) GEMM2 -> out (mixed HMMA + dp4a)
    k_gemm2<<<dim3(HDIM / 128, T_TOK / 128), 512, SM2>>>(out);
}

// round 10
// speedup vs baseline: 1.4713x; 1.4713x over previous
#include <cuda_runtime.h>
#include <cuda_bf16.h>
#include <math.h>
#include <stdint.h>

// Problem dims (fixed): x [2,2048,2048] -> T=4096 tokens, H=2048, I=8192
#define T_TOK 4096
#define HDIM  2048
#define IDIM  8192
#define NGATE 16384   // 2*I rows in w_gate
#define PITCH 80      // padded smem row pitch (bytes) for 64B k-chunks

// ---------------- device scratch (static, allocation-free) ----------------
__device__ double        d_part[3072];    // per-block |w| partial sums
__device__ float         d_wscale[2];
__device__ float         d_winv[2];
__device__ __nv_bfloat16 d_wqg[(long long)NGATE * HDIM];  // ternary gate/up (bf16 ints)
__device__ __nv_bfloat16 d_wqd[(long long)HDIM * IDIM];   // ternary down
__device__ __nv_bfloat16 d_xq[(long long)T_TOK * HDIM];   // quant acts L1 (bf16 ints)
__device__ float         d_as1[T_TOK];
__device__ float         d_h[(long long)T_TOK * IDIM];    // SwiGLU output (fp32)
__device__ __nv_bfloat16 d_hq[(long long)T_TOK * IDIM];   // quant acts L2
__device__ float         d_as2[T_TOK];

// ---------------- PTX helpers (base PTX only; valid at sm_103 target) ------
__device__ __forceinline__ uint32_t smem_u32(const void* p) {
    return (uint32_t)__cvta_generic_to_shared(p);
}
__device__ __forceinline__ void cpa16(uint32_t s, const void* g) {
    asm volatile("cp.async.cg.shared.global [%0], [%1], 16;" :: "r"(s), "l"(g));
}
__device__ __forceinline__ void cp_commit() {
    asm volatile("cp.async.commit_group;");
}
__device__ __forceinline__ void ldsm4(uint32_t* r, uint32_t a) {
    asm volatile("ldmatrix.sync.aligned.m8n8.x4.shared.b16 {%0,%1,%2,%3}, [%4];"
        : "=r"(r[0]), "=r"(r[1]), "=r"(r[2]), "=r"(r[3]) : "r"(a));
}
__device__ __forceinline__ void mma_bf16(float* c, const uint32_t* a, const uint32_t* b) {
    asm volatile(
        "mma.sync.aligned.m16n8k16.row.col.f32.bf16.bf16.f32 "
        "{%0,%1,%2,%3}, {%4,%5,%6,%7}, {%8,%9}, {%0,%1,%2,%3};"
        : "+f"(c[0]), "+f"(c[1]), "+f"(c[2]), "+f"(c[3])
        : "r"(a[0]), "r"(a[1]), "r"(a[2]), "r"(a[3]), "r"(b[0]), "r"(b[1]));
}
__device__ __forceinline__ float silu_mul(float g, float v) {
    return g / (1.f + expf(-g)) * v;
}

// ---------------- scalar pre-passes ----------------
// partial |w| sums: blocks [0,2048) gate, [2048,3072) down; no atomics
__global__ void k_abssum2(const float* __restrict__ wg, const float* __restrict__ wd) {
    const float* w; long long n; int bid, nb;
    if (blockIdx.x < 2048) { w = wg; n = (long long)NGATE * HDIM; bid = blockIdx.x; nb = 2048; }
    else                   { w = wd; n = (long long)HDIM * IDIM;  bid = blockIdx.x - 2048; nb = 1024; }
    float s = 0.f;
    long long stride = (long long)nb * 256;
    for (long long i = (long long)bid * 256 + threadIdx.x; i < n; i += stride)
        s += fabsf(w[i]);
    #pragma unroll
    for (int o = 16; o > 0; o >>= 1) s += __shfl_xor_sync(0xffffffffu, s, o);
    __shared__ double sb[8];
    int wid = threadIdx.x >> 5, lane = threadIdx.x & 31;
    if (lane == 0) sb[wid] = (double)s;
    __syncthreads();
    if (threadIdx.x == 0) {
        double t = 0.0;
        #pragma unroll
        for (int i = 0; i < 8; i++) t += sb[i];
        d_part[blockIdx.x] = t;
    }
}

// single-block reduce of partials -> scales
__global__ void k_wscale() {
    double s0 = 0.0, s1 = 0.0;
    for (int i = threadIdx.x; i < 2048; i += 256) s0 += d_part[i];
    for (int i = 2048 + threadIdx.x; i < 3072; i += 256) s1 += d_part[i];
    #pragma unroll
    for (int o = 16; o > 0; o >>= 1) {
        s0 += __shfl_xor_sync(0xffffffffu, s0, o);
        s1 += __shfl_xor_sync(0xffffffffu, s1, o);
    }
    __shared__ double sb0[8], sb1[8];
    int wid = threadIdx.x >> 5, lane = threadIdx.x & 31;
    if (lane == 0) { sb0[wid] = s0; sb1[wid] = s1; }
    __syncthreads();
    if (threadIdx.x == 0) {
        double t0 = 0.0, t1 = 0.0;
        #pragma unroll
        for (int i = 0; i < 8; i++) { t0 += sb0[i]; t1 += sb1[i]; }
        float m0 = (float)(t0 / (double)((long long)NGATE * HDIM));
        float m1 = (float)(t1 / (double)((long long)HDIM * IDIM));
        float sc0 = 1.f / fmaxf(m0, 1e-5f);
        float sc1 = 1.f / fmaxf(m1, 1e-5f);
        d_wscale[0] = sc0; d_wscale[1] = sc1;
        d_winv[0] = 1.f / sc0; d_winv[1] = 1.f / sc1;
    }
}

// ternarize both weights -> bf16; blocks [0,4096) gate, [4096,6144) down
__global__ void k_wquant2(const float4* __restrict__ wg, const float4* __restrict__ wd) {
    const float4* w; long long n4; int which, bid, nb;
    if (blockIdx.x < 4096) { w = wg; n4 = (long long)NGATE * HDIM / 4; which = 0; bid = blockIdx.x; nb = 4096; }
    else                   { w = wd; n4 = (long long)HDIM * IDIM / 4;  which = 1; bid = blockIdx.x - 4096; nb = 2048; }
    float s = d_wscale[which];
    __nv_bfloat162* q2 = reinterpret_cast<__nv_bfloat162*>(which ? d_wqd : d_wqg);
    long long stride = (long long)nb * 256;
    for (long long i = (long long)bid * 256 + threadIdx.x; i < n4; i += stride) {
        float4 v = w[i];
        float a = fminf(fmaxf(rintf(v.x * s), -1.f), 1.f);
        float b = fminf(fmaxf(rintf(v.y * s), -1.f), 1.f);
        float c = fminf(fmaxf(rintf(v.z * s), -1.f), 1.f);
        float d = fminf(fmaxf(rintf(v.w * s), -1.f), 1.f);
        q2[i * 2 + 0] = __floats2bfloat162_rn(a, b);
        q2[i * 2 + 1] = __floats2bfloat162_rn(c, d);
    }
}

// ---------------- block reduction helper ----------------
__device__ __forceinline__ float block_reduce(float v, bool isMax) {
    __shared__ float sb[8];
    __syncthreads();
    #pragma unroll
    for (int o = 16; o > 0; o >>= 1) {
        float t = __shfl_xor_sync(0xffffffffu, v, o);
        v = isMax ? fmaxf(v, t) : (v + t);
    }
    int wid = threadIdx.x >> 5, lane = threadIdx.x & 31;
    if (lane == 0) sb[wid] = v;
    __syncthreads();
    float r;
    if (isMax) {
        r = fmaxf(fmaxf(fmaxf(sb[0], sb[1]), fmaxf(sb[2], sb[3])),
                  fmaxf(fmaxf(sb[4], sb[5]), fmaxf(sb[6], sb[7])));
    } else {
        r = sb[0] + sb[1] + sb[2] + sb[3] + sb[4] + sb[5] + sb[6] + sb[7];
    }
    return r;
}

// ---------------- RMSNorm + per-token int8 quant (bf16 ints out) -----------
template <int HID, int VPT>
__global__ void __launch_bounds__(256) k_actquant(
    const float* __restrict__ x, const float* __restrict__ g,
    __nv_bfloat16* __restrict__ q, float* __restrict__ ascale)
{
    long long t = blockIdx.x;
    const float* xr = x + t * HID;
    float v[VPT];
    float ss = 0.f;
    #pragma unroll
    for (int j = 0; j < VPT; j++) {
        float f = xr[threadIdx.x + j * 256];
        v[j] = f;
        ss += f * f;
    }
    float var = block_reduce(ss, false) * (1.f / (float)HID);
    float r = rsqrtf(var + 1e-5f);
    float amax = 0.f;
    #pragma unroll
    for (int j = 0; j < VPT; j++) {
        float xn = v[j] * r * g[threadIdx.x + j * 256];
        v[j] = xn;
        amax = fmaxf(amax, fabsf(xn));
    }
    amax = block_reduce(amax, true);
    float s = 127.f / fmaxf(amax, 1e-5f);
    __nv_bfloat16* qr = q + t * HID;
    #pragma unroll
    for (int j = 0; j < VPT; j++) {
        float qf = fminf(fmaxf(rintf(v[j] * s), -128.f), 127.f);
        qr[threadIdx.x + j * 256] = __float2bfloat16(qf);  // exact int
    }
    if (threadIdx.x == 0) ascale[t] = 1.f / s;
}

// =====================================================================
// GEMM1 (HMMA, 16 warps = 4/SMSP): xq @ w_gate^T fused with SwiGLU.
// CTA tile M=128 x N=128 h-cols (gate AND v). Warp grid 2(m) x 8(n),
// warp tile M=64 x N=16 per operand. k-chunk = 32 bf16 (64B rows).
// Stage (S1=30720): A16 @0 (128x80) | G16 @10240 | V16 @20480. 2 stages.
// =====================================================================
#define S1 30720

#define G1_LOAD(buf, kt)                                                     \
{                                                                            \
    const uint32_t st = sb + (buf) * S1;                                     \
    const int row = tid >> 2, seg = tid & 3;                                 \
    const long long go = (long long)row * (HDIM * 2) + (kt) * 64 + seg * 16; \
    const uint32_t so = (uint32_t)row * PITCH + seg * 16;                    \
    cpa16(st + so,          Ag16 + go);                                      \
    cpa16(st + 10240 + so,  Gg16 + go);                                      \
    cpa16(st + 20480 + so,  Vg16 + go);                                      \
    cp_commit();                                                             \
}

__global__ void __launch_bounds__(512, 1) k_gemm1() {
    extern __shared__ char smem[];
    const int tid = threadIdx.x;
    const int wid = tid >> 5, l = tid & 31;
    const int wm = wid >> 3, wn = wid & 7;     // 2 x 8 warp grid
    const int mBase = blockIdx.y * 128;
    const int nBase = blockIdx.x * 128;
    const uint32_t sb = smem_u32(smem);

    const char* Ag16 = (const char*)d_xq  + (long long)mBase * (HDIM * 2);
    const char* Gg16 = (const char*)d_wqg + (long long)nBase * (HDIM * 2);
    const char* Vg16 = (const char*)d_wqg + (long long)(nBase + IDIM) * (HDIM * 2);

    float accg[4][2][4] = {};
    float accv[4][2][4] = {};

    const uint32_t aoff = (uint32_t)(wm * 64 + (l & 15)) * PITCH + (l >> 4) * 16;
    const uint32_t boff = (uint32_t)(wn * 16 + ((l >> 4) << 3) + (l & 7)) * PITCH
                        + ((l >> 3) & 1) * 16;

    const int NK = HDIM / 32;   // 64 chunks
    G1_LOAD(0, 0);

    for (int kt = 0; kt < NK; kt++) {
        const int buf = kt & 1;
        if (kt + 1 < NK) {
            G1_LOAD(buf ^ 1, kt + 1);
            asm volatile("cp.async.wait_group 1;");
        } else {
            asm volatile("cp.async.wait_group 0;");
        }
        __syncthreads();
        const uint32_t As = sb + buf * S1;
        const uint32_t Gs = As + 10240, Vs = As + 20480;
        #pragma unroll
        for (int ks = 0; ks < 2; ks++) {
            uint32_t a[4][4];
            #pragma unroll
            for (int mf = 0; mf < 4; mf++)
                ldsm4(a[mf], As + aoff + mf * (16 * PITCH) + ks * 32);
            uint32_t bg[4], bv[4];
            ldsm4(bg, Gs + boff + ks * 32);
            ldsm4(bv, Vs + boff + ks * 32);
            #pragma unroll
            for (int mf = 0; mf < 4; mf++) {
                #pragma unroll
                for (int nf = 0; nf < 2; nf++) {
                    mma_bf16(accg[mf][nf], a[mf], &bg[nf * 2]);
                    mma_bf16(accv[mf][nf], a[mf], &bv[nf * 2]);
                }
            }
        }
        __syncthreads();
    }
    #undef G1_LOAD

    // epilogue: dequant + SwiGLU -> d_h (fp32)
    const float wiv = d_winv[0];
    #pragma unroll
    for (int mf = 0; mf < 4; mf++) {
        const int r0 = mBase + wm * 64 + mf * 16 + (l >> 2);
        const float s0 = d_as1[r0] * wiv;
        const float s1 = d_as1[r0 + 8] * wiv;
        float* h0 = d_h + (long long)r0 * IDIM;
        float* h1 = d_h + (long long)(r0 + 8) * IDIM;
        #pragma unroll
        for (int nf = 0; nf < 2; nf++) {
            const int c0 = nBase + wn * 16 + nf * 8 + (l & 3) * 2;
            float2 o0, o1;
            o0.x = silu_mul(accg[mf][nf][0] * s0, accv[mf][nf][0] * s0);
            o0.y = silu_mul(accg[mf][nf][1] * s0, accv[mf][nf][1] * s0);
            o1.x = silu_mul(accg[mf][nf][2] * s1, accv[mf][nf][2] * s1);
            o1.y = silu_mul(accg[mf][nf][3] * s1, accv[mf][nf][3] * s1);
            *(float2*)(h0 + c0) = o0;
            *(float2*)(h1 + c0) = o1;
        }
    }
}

// =====================================================================
// GEMM2 (HMMA, 16 warps): hq @ w_down^T -> fp32 out. Warp tile M64 x N16.
// Stage (S2=20480): A16 @0 | B16 @10240. 2 stages.
// =====================================================================
#define S2 20480

#define G2_LOAD(buf, kt)                                                     \
{                                                                            \
    const uint32_t st = sb + (buf) * S2;                                     \
    const int row = tid >> 2, seg = tid & 3;                                 \
    const long long go = (long long)row * (IDIM * 2) + (kt) * 64 + seg * 16; \
    const uint32_t so = (uint32_t)row * PITCH + seg * 16;                    \
    cpa16(st + so,          Ag16 + go);                                      \
    cpa16(st + 10240 + so,  Bg16 + go);                                      \
    cp_commit();                                                             \
}

__global__ void __launch_bounds__(512, 1) k_gemm2(float* __restrict__ out) {
    extern __shared__ char smem[];
    const int tid = threadIdx.x;
    const int wid = tid >> 5, l = tid & 31;
    const int wm = wid >> 3, wn = wid & 7;
    const int mBase = blockIdx.y * 128;
    const int nBase = blockIdx.x * 128;
    const uint32_t sb = smem_u32(smem);

    const char* Ag16 = (const char*)d_hq  + (long long)mBase * (IDIM * 2);
    const char* Bg16 = (const char*)d_wqd + (long long)nBase * (IDIM * 2);

    float acc[4][2][4] = {};

    const uint32_t aoff = (uint32_t)(wm * 64 + (l & 15)) * PITCH + (l >> 4) * 16;
    const uint32_t boff = (uint32_t)(wn * 16 + ((l >> 4) << 3) + (l & 7)) * PITCH
                        + ((l >> 3) & 1) * 16;

    const int NK = IDIM / 32;   // 256 chunks
    G2_LOAD(0, 0);

    for (int kt = 0; kt < NK; kt++) {
        const int buf = kt & 1;
        if (kt + 1 < NK) {
            G2_LOAD(buf ^ 1, kt + 1);
            asm volatile("cp.async.wait_group 1;");
        } else {
            asm volatile("cp.async.wait_group 0;");
        }
        __syncthreads();
        const uint32_t As = sb + buf * S2;
        const uint32_t Bs = As + 10240;
        #pragma unroll
        for (int ks = 0; ks < 2; ks++) {
            uint32_t a[4][4];
            #pragma unroll
            for (int mf = 0; mf < 4; mf++)
                ldsm4(a[mf], As + aoff + mf * (16 * PITCH) + ks * 32);
            uint32_t b[4];
            ldsm4(b, Bs + boff + ks * 32);
            #pragma unroll
            for (int mf = 0; mf < 4; mf++) {
                #pragma unroll
                for (int nf = 0; nf < 2; nf++)
                    mma_bf16(acc[mf][nf], a[mf], &b[nf * 2]);
            }
        }
        __syncthreads();
    }
    #undef G2_LOAD

    const float wiv = d_winv[1];
    #pragma unroll
    for (int mf = 0; mf < 4; mf++) {
        const int r0 = mBase + wm * 64 + mf * 16 + (l >> 2);
        const float s0 = d_as2[r0] * wiv;
        const float s1 = d_as2[r0 + 8] * wiv;
        float* o0p = out + (long long)r0 * HDIM;
        float* o1p = out + (long long)(r0 + 8) * HDIM;
        #pragma unroll
        for (int nf = 0; nf < 2; nf++) {
            const int c0 = nBase + wn * 16 + nf * 8 + (l & 3) * 2;
            float2 o0, o1;
            o0.x = acc[mf][nf][0] * s0;
            o0.y = acc[mf][nf][1] * s0;
            o1.x = acc[mf][nf][2] * s1;
            o1.y = acc[mf][nf][3] * s1;
            *(float2*)(o0p + c0) = o0;
            *(float2*)(o1p + c0) = o1;
        }
    }
}

// ---------------- host ----------------
extern "C" void kernel_launch(void* const* d_in, const int* in_sizes, int n_in,
                              void* d_out, int out_size) {
    const float* x      = (const float*)d_in[0];
    const float* w_gate = (const float*)d_in[1];
    const float* g_gate = (const float*)d_in[2];
    const float* w_down = (const float*)d_in[3];
    const float* g_down = (const float*)d_in[4];
    float* out = (float*)d_out;

    __nv_bfloat16* p_xq = nullptr; float* p_as1 = nullptr;
    float* p_h = nullptr; __nv_bfloat16* p_hq = nullptr; float* p_as2 = nullptr;
    cudaGetSymbolAddress((void**)&p_xq,  d_xq);
    cudaGetSymbolAddress((void**)&p_as1, d_as1);
    cudaGetSymbolAddress((void**)&p_h,   d_h);
    cudaGetSymbolAddress((void**)&p_hq,  d_hq);
    cudaGetSymbolAddress((void**)&p_as2, d_as2);

    const int SM1 = 2 * S1;   // 61440
    const int SM2 = 2 * S2;   // 40960
    cudaFuncSetAttribute(k_gemm1, cudaFuncAttributeMaxDynamicSharedMemorySize, SM1);
    cudaFuncSetAttribute(k_gemm2, cudaFuncAttributeMaxDynamicSharedMemorySize, SM2);

    // 1) weight scales (no atomics) + ternarize
    k_abssum2<<<3072, 256>>>(w_gate, w_down);
    k_wscale<<<1, 256>>>();
    k_wquant2<<<6144, 256>>>((const float4*)w_gate, (const float4*)w_down);

    // 2) RMSNorm + quantize x
    k_actquant<HDIM, HDIM / 256><<<T_TOK, 256>>>(x, g_gate, p_xq, p_as1);

    // 3) GEMM1 + SwiGLU -> h  (16 warps, 4 HMMA warps/SMSP)
    k_gemm1<<<dim3(IDIM / 128, T_TOK / 128), 512, SM1>>>();

    // 4) RMSNorm + quantize h
    k_actquant<IDIM, IDIM / 256><<<T_TOK, 256>>>(p_h, g_down, p_hq, p_as2);

    // 5) GEMM2 -> out
    k_gemm2<<<dim3(HDIM / 128, T_TOK / 128), 512, SM2>>>(out);
}